// round 13
// baseline (speedup 1.0000x reference)
#include <cuda_runtime.h>
#include <cuda_bf16.h>
#include <cuda_fp16.h>
#include <cstdint>

#define NN   100000
#define D    128
#define MAXE 3400000
#define NT   ((NN + 127) / 128)
#define TILE_U4 2048   // uint4 per 32KB bf16 128x128 image

// ---------------------------------------------------------------------------
// Allocation-free scratch
// ---------------------------------------------------------------------------
__device__ __half g_xh[(size_t)NN * D];          // fp16 copy of x
__device__ uint4  g_a_hi[(size_t)NT * TILE_U4];  // gathered h, bf16 hi image
__device__ uint4  g_a_lo[(size_t)NT * TILE_U4];  // gathered h, bf16 lo image
__device__ int    g_cnt[NN];
__device__ int    g_inc[NN];
__device__ int    g_rs[NN];
__device__ int    g_cur[NN];
__device__ int    g_srcs[MAXE];
__device__ int    g_bsums[128];
__device__ uint4  g_w_hi[3 * TILE_U4];
__device__ uint4  g_w_lo[3 * TILE_U4];

static __device__ __forceinline__ uint32_t s2u(const void* p) {
    uint32_t a;
    asm("{ .reg .u64 t; cvta.to.shared.u64 t, %1; cvt.u32.u64 %0, t; }"
        : "=r"(a) : "l"(p));
    return a;
}

static __device__ __forceinline__ uint32_t pack_bf2(float a, float b) {
    __nv_bfloat162 t = __floats2bfloat162_rn(a, b);
    return *(uint32_t*)&t;
}

static __device__ __forceinline__ void mma16816(float* c, const uint32_t* a,
                                                uint32_t b0, uint32_t b1) {
    asm volatile(
        "mma.sync.aligned.m16n8k16.row.col.f32.bf16.bf16.f32 "
        "{%0,%1,%2,%3}, {%4,%5,%6,%7}, {%8,%9}, {%0,%1,%2,%3};"
        : "+f"(c[0]), "+f"(c[1]), "+f"(c[2]), "+f"(c[3])
        : "r"(a[0]), "r"(a[1]), "r"(a[2]), "r"(a[3]), "r"(b0), "r"(b1));
}

static __device__ __forceinline__ void ldsm_x4(uint32_t* r, uint32_t addr) {
    asm volatile("ldmatrix.sync.aligned.m8n8.x4.shared.b16 {%0,%1,%2,%3}, [%4];"
                 : "=r"(r[0]), "=r"(r[1]), "=r"(r[2]), "=r"(r[3]) : "r"(addr));
}
static __device__ __forceinline__ void ldsm_x4t(uint32_t* r, uint32_t addr) {
    asm volatile("ldmatrix.sync.aligned.m8n8.x4.trans.shared.b16 {%0,%1,%2,%3}, [%4];"
                 : "=r"(r[0]), "=r"(r[1]), "=r"(r[2]), "=r"(r[3]) : "r"(addr));
}

static __device__ __forceinline__ void cpa16(uint32_t dst, const void* src) {
    asm volatile("cp.async.cg.shared.global [%0], [%1], 16;"
                 :: "r"(dst), "l"(src) : "memory");
}

// tile byte offset: row-major 128x128 bf16, 256B/row, XOR-swizzled 16B groups
static __device__ __forceinline__ uint32_t toff(int row, int g) {
    return (uint32_t)row * 256u + (uint32_t)((g ^ (row & 7)) << 4);
}

// ---------------------------------------------------------------------------
// Merged prep: [0,nbX) x->fp16 copy; [nbX,nbX+nbE) hist; rest: W images.
// ---------------------------------------------------------------------------
__global__ void prep_hist_kernel(const float4* __restrict__ x4,
                                 uint2* __restrict__ xh,
                                 const int* __restrict__ ei, int nE,
                                 const float* __restrict__ W1,
                                 const float* __restrict__ W2,
                                 const float* __restrict__ W3,
                                 int nbX, int nbE) {
    int b = blockIdx.x;
    if (b < nbX) {
        int i = b * 256 + threadIdx.x;
        if (i < NN * D / 4) {
            float4 v = x4[i];
            __half2 h0 = __floats2half2_rn(v.x, v.y);
            __half2 h1 = __floats2half2_rn(v.z, v.w);
            xh[i] = make_uint2(*(uint32_t*)&h0, *(uint32_t*)&h1);
        }
    } else if (b < nbX + nbE) {
        int e = (b - nbX) * 256 + threadIdx.x;
        if (e < nE) atomicAdd(&g_cnt[ei[nE + e]], 1);
    } else {
        int idx = (b - nbX - nbE) * 256 + threadIdx.x;   // 48 blocks: 3*4096
        if (idx < 3 * 4096) {
            int w = idx >> 12, i = idx & 4095;
            const float* W = (w == 0) ? W1 : (w == 1) ? W2 : W3;
            char* hi = (char*)g_w_hi + (size_t)w * 32768;
            char* lo = (char*)g_w_lo + (size_t)w * 32768;
            int k = i >> 5, c4 = i & 31;
            float4 v = ((const float4*)W)[i];
            float hx = __bfloat162float(__float2bfloat16(v.x));
            float hy = __bfloat162float(__float2bfloat16(v.y));
            float hz = __bfloat162float(__float2bfloat16(v.z));
            float hw = __bfloat162float(__float2bfloat16(v.w));
            uint2 hv = make_uint2(pack_bf2(v.x, v.y), pack_bf2(v.z, v.w));
            uint2 lv = make_uint2(pack_bf2(v.x - hx, v.y - hy),
                                  pack_bf2(v.z - hz, v.w - hw));
            uint32_t off = toff(k, c4 >> 1) + (c4 & 1) * 8;
            *(uint2*)(hi + off) = hv;
            *(uint2*)(lo + off) = lv;
        }
    }
}

// ---------------------------------------------------------------------------
// CSR scans + fill
// ---------------------------------------------------------------------------
__global__ void scan1_kernel() {
    __shared__ int sm[1024];
    int t = threadIdx.x, b = blockIdx.x;
    int i = b * 1024 + t;
    sm[t] = (i < NN) ? g_cnt[i] : 0;
    __syncthreads();
    #pragma unroll
    for (int off = 1; off < 1024; off <<= 1) {
        int add = (t >= off) ? sm[t - off] : 0;
        __syncthreads();
        sm[t] += add;
        __syncthreads();
    }
    if (i < NN) g_inc[i] = sm[t];
    if (t == 1023) g_bsums[b] = sm[t];
}

__global__ void scan3_kernel() {
    __shared__ int base_sh;
    int t = threadIdx.x;
    int chunk = (int)(blockIdx.x >> 2);
    if (t < 32) {
        int s = 0;
        for (int j = t; j < chunk; j += 32) s += g_bsums[j];
        #pragma unroll
        for (int o = 16; o; o >>= 1) s += __shfl_down_sync(0xFFFFFFFFu, s, o);
        if (t == 0) base_sh = s;
    }
    __syncthreads();
    int i = blockIdx.x * blockDim.x + t;
    if (i < NN) {
        int rs = g_inc[i] - g_cnt[i] + base_sh;
        g_rs[i] = rs;
        g_cur[i] = rs;
    }
}

__global__ void fill_kernel(const int* __restrict__ ei, int nE) {
    int e = blockIdx.x * blockDim.x + threadIdx.x;
    if (e < nE) {
        int s = ei[e], d = ei[nE + e];
        int pos = atomicAdd(&g_cur[d], 1);
        g_srcs[pos] = s;
    }
}

// ---------------------------------------------------------------------------
// Gather: warp per node, fp16 neighbor reads, fp32 accum; emits bf16 hi/lo
// pre-swizzled tile images (mlp3's A operand, verbatim-copyable).
// ---------------------------------------------------------------------------
static __device__ __forceinline__ void acc_half4(float4& a, uint2 raw) {
    float2 f0 = __half22float2(*(__half2*)&raw.x);
    float2 f1 = __half22float2(*(__half2*)&raw.y);
    a.x += f0.x; a.y += f0.y; a.z += f1.x; a.w += f1.y;
}

__global__ __launch_bounds__(256)
void gather_kernel(const float* __restrict__ x) {
    int n = blockIdx.x * 8 + (threadIdx.x >> 5);
    if (n >= NN) return;
    int lane = threadIdx.x & 31;
    const uint2* xh = (const uint2*)g_xh;

    float4 a0 = ((const float4*)x)[(size_t)n * 32 + lane];   // self, fp32
    float4 a1 = make_float4(0.f, 0.f, 0.f, 0.f);
    float4 a2 = a1, a3 = a1;

    int start = g_rs[n], c = g_cnt[n];
    const int* sp = g_srcs + start;
    int j = 0;
    for (; j + 4 <= c; j += 4) {
        int s0 = sp[j], s1 = sp[j + 1], s2 = sp[j + 2], s3 = sp[j + 3];
        uint2 v0 = xh[(size_t)s0 * 32 + lane];
        uint2 v1 = xh[(size_t)s1 * 32 + lane];
        uint2 v2 = xh[(size_t)s2 * 32 + lane];
        uint2 v3 = xh[(size_t)s3 * 32 + lane];
        acc_half4(a0, v0); acc_half4(a1, v1);
        acc_half4(a2, v2); acc_half4(a3, v3);
    }
    for (; j < c; j++)
        acc_half4(a0, xh[(size_t)sp[j] * 32 + lane]);

    float s[4];
    s[0] = (a0.x + a1.x) + (a2.x + a3.x);
    s[1] = (a0.y + a1.y) + (a2.y + a3.y);
    s[2] = (a0.z + a1.z) + (a2.z + a3.z);
    s[3] = (a0.w + a1.w) + (a2.w + a3.w);

    float hf[4];
    #pragma unroll
    for (int i = 0; i < 4; i++)
        hf[i] = __bfloat162float(__float2bfloat16(s[i]));
    uint2 hv = make_uint2(pack_bf2(s[0], s[1]), pack_bf2(s[2], s[3]));
    uint2 lv = make_uint2(pack_bf2(s[0] - hf[0], s[1] - hf[1]),
                          pack_bf2(s[2] - hf[2], s[3] - hf[3]));

    int tile = n >> 7, row = n & 127;
    uint32_t off = toff(row, lane >> 1) + (lane & 1) * 8;
    size_t tb = (size_t)tile * 32768;
    *(uint2*)((char*)g_a_hi + tb + off) = hv;
    *(uint2*)((char*)g_a_lo + tb + off) = lv;
}

// ---------------------------------------------------------------------------
// GEMM building blocks (split-bf16 HMMA, 128x128 tile, K=128), R9/R12 shapes.
// lo image always at +32768 within its region.
// ---------------------------------------------------------------------------
static __device__ __forceinline__ void mma_mainloop(
    uint32_t sb, uint32_t w_off, uint32_t a_off, int wid, int lane,
    float acc[16][4]) {
    #pragma unroll
    for (int i = 0; i < 16; i++)
        #pragma unroll
        for (int j = 0; j < 4; j++) acc[i][j] = 0.f;

    int mrow = wid * 16;
    int arow = mrow + (lane & 15);
    int asel = lane >> 4;
    int axor = arow & 7;
    uint32_t a_base = sb + a_off + (uint32_t)arow * 256u;
    int brow = lane & 15;
    int bsel = lane >> 4;

    #pragma unroll
    for (int ks = 0; ks < 8; ks++) {
        uint32_t ag = (uint32_t)(((ks * 2 + asel) ^ axor) << 4);
        uint32_t ahi[4], alo[4];
        ldsm_x4(ahi, a_base + ag);
        ldsm_x4(alo, a_base + 32768u + ag);

        int brr = ks * 16 + brow;
        uint32_t b_base = sb + w_off + (uint32_t)brr * 256u;
        int bxor = brr & 7;

        #pragma unroll
        for (int p = 0; p < 8; p++) {
            uint32_t bg = (uint32_t)(((p * 2 + bsel) ^ bxor) << 4);
            uint32_t bh[4], bl[4];
            ldsm_x4t(bh, b_base + bg);
            ldsm_x4t(bl, b_base + 32768u + bg);
            mma16816(acc[2 * p],     ahi, bh[0], bh[1]);
            mma16816(acc[2 * p + 1], ahi, bh[2], bh[3]);
            mma16816(acc[2 * p],     ahi, bl[0], bl[1]);
            mma16816(acc[2 * p + 1], ahi, bl[2], bl[3]);
            mma16816(acc[2 * p],     alo, bh[0], bh[1]);
            mma16816(acc[2 * p + 1], alo, bh[2], bh[3]);
        }
    }
}

// bias + relu -> fp32 gmem rows
static __device__ __forceinline__ void epilogue_gmem(
    float acc[16][4], const float* bs, int wid, int lane, int row0,
    float* __restrict__ hout) {
    int rbase = wid * 16 + (lane >> 2);
    int col0 = (lane & 3) * 2;
    #pragma unroll
    for (int half = 0; half < 2; half++) {
        int grow = row0 + rbase + half * 8;
        if (grow < NN) {
            float* op = hout + (size_t)grow * D;
            #pragma unroll
            for (int nt = 0; nt < 16; nt++) {
                int c = nt * 8 + col0;
                float2 o;
                o.x = fmaxf(acc[nt][half * 2 + 0] + bs[c], 0.f);
                o.y = fmaxf(acc[nt][half * 2 + 1] + bs[c + 1], 0.f);
                *(float2*)(op + c) = o;
            }
        }
    }
}

// bias + relu -> bf16 hi/lo smem tile images (next GEMM's A operand)
static __device__ __forceinline__ void epilogue_smem(
    float acc[16][4], const float* bs, int wid, int lane,
    char* smem, uint32_t a_off) {
    int rbase = wid * 16 + (lane >> 2);
    int col0 = (lane & 3) * 2;
    #pragma unroll
    for (int half = 0; half < 2; half++) {
        int row = rbase + half * 8;
        #pragma unroll
        for (int nt = 0; nt < 16; nt++) {
            int c = nt * 8 + col0;
            float v0 = fmaxf(acc[nt][half * 2 + 0] + bs[c], 0.f);
            float v1 = fmaxf(acc[nt][half * 2 + 1] + bs[c + 1], 0.f);
            float h0 = __bfloat162float(__float2bfloat16(v0));
            float h1 = __bfloat162float(__float2bfloat16(v1));
            uint32_t off = toff(row, nt) + (uint32_t)col0 * 2u;
            *(uint32_t*)(smem + a_off + off) = pack_bf2(v0, v1);
            *(uint32_t*)(smem + a_off + 32768u + off) = pack_bf2(v0 - h0, v1 - h1);
        }
    }
}

// ---------------------------------------------------------------------------
// All 3 layers in one kernel, one CTA per 128-row tile (R12 structure).
// Change vs R12: A staged as verbatim cp.async images (no fp32 load+convert).
// ---------------------------------------------------------------------------
#define R1_OFF 0u
#define R2_OFF 65536u
#define R3_OFF 131072u
#define B1_OFF 196608u
#define B2_OFF 197120u
#define B3_OFF 197632u
#define M3_SM  (196608 + 1536)

__global__ __launch_bounds__(256, 1)
void mlp3_kernel(const uint4* __restrict__ Ahi, const uint4* __restrict__ Alo,
                 const uint4* __restrict__ W1hi, const uint4* __restrict__ W1lo,
                 const uint4* __restrict__ W2hi, const uint4* __restrict__ W2lo,
                 const uint4* __restrict__ W3hi, const uint4* __restrict__ W3lo,
                 const float* __restrict__ b1, const float* __restrict__ b2,
                 const float* __restrict__ b3,
                 float* __restrict__ out) {
    extern __shared__ char smem[];
    uint32_t sb = s2u(smem);
    int tid = threadIdx.x, wid = tid >> 5, lane = tid & 31;
    int row0 = blockIdx.x * 128;

    const uint4* At_hi = Ahi + (size_t)blockIdx.x * TILE_U4;
    const uint4* At_lo = Alo + (size_t)blockIdx.x * TILE_U4;

    // one cp.async group: W1, W2, A (all verbatim 16B, swizzle preserved)
    #pragma unroll
    for (int t = 0; t < 8; t++) {
        int i = tid + t * 256;
        cpa16(sb + R1_OFF + (uint32_t)i * 16u,          W1hi + i);
        cpa16(sb + R1_OFF + 32768u + (uint32_t)i * 16u, W1lo + i);
        cpa16(sb + R2_OFF + (uint32_t)i * 16u,          W2hi + i);
        cpa16(sb + R2_OFF + 32768u + (uint32_t)i * 16u, W2lo + i);
        cpa16(sb + R3_OFF + (uint32_t)i * 16u,          At_hi + i);
        cpa16(sb + R3_OFF + 32768u + (uint32_t)i * 16u, At_lo + i);
    }
    asm volatile("cp.async.commit_group;" ::: "memory");
    if (tid < 32)       ((float4*)(smem + B1_OFF))[tid]      = ((const float4*)b1)[tid];
    else if (tid < 64)  ((float4*)(smem + B2_OFF))[tid - 32] = ((const float4*)b2)[tid - 32];
    else if (tid < 96)  ((float4*)(smem + B3_OFF))[tid - 64] = ((const float4*)b3)[tid - 64];
    asm volatile("cp.async.wait_group 0;" ::: "memory");
    __syncthreads();

    float acc[16][4];
    // GEMM1
    mma_mainloop(sb, R1_OFF, R3_OFF, wid, lane, acc);
    __syncthreads();   // done reading R1(W1), R3(A)

    // W3 -> R3, hidden under GEMM2
    #pragma unroll
    for (int t = 0; t < 8; t++) {
        int i = tid + t * 256;
        cpa16(sb + R3_OFF + (uint32_t)i * 16u,          W3hi + i);
        cpa16(sb + R3_OFF + 32768u + (uint32_t)i * 16u, W3lo + i);
    }
    asm volatile("cp.async.commit_group;" ::: "memory");

    epilogue_smem(acc, (const float*)(smem + B1_OFF), wid, lane, smem, R1_OFF);
    __syncthreads();   // A' visible

    // GEMM2
    mma_mainloop(sb, R2_OFF, R1_OFF, wid, lane, acc);
    asm volatile("cp.async.wait_group 0;" ::: "memory");
    __syncthreads();   // done reading R1(A'); W3 landed

    epilogue_smem(acc, (const float*)(smem + B2_OFF), wid, lane, smem, R1_OFF);
    __syncthreads();   // A'' visible

    // GEMM3
    mma_mainloop(sb, R3_OFF, R1_OFF, wid, lane, acc);
    epilogue_gmem(acc, (const float*)(smem + B3_OFF), wid, lane, row0, out);
}

// ---------------------------------------------------------------------------
extern "C" void kernel_launch(void* const* d_in, const int* in_sizes, int n_in,
                              void* d_out, int out_size) {
    const float* x  = (const float*)d_in[0];
    const float* W1 = (const float*)d_in[1];
    const float* b1 = (const float*)d_in[2];
    const float* W2 = (const float*)d_in[3];
    const float* b2 = (const float*)d_in[4];
    const float* W3 = (const float*)d_in[5];
    const float* b3 = (const float*)d_in[6];
    const int*   ei = (const int*)d_in[7];   // int32 (JAX x64 disabled)
    float* out = (float*)d_out;

    int nE = in_sizes[7] / 2;
    if (nE > MAXE) nE = MAXE;

    int* cnt;
    uint2* xh;
    uint4 *wHi, *wLo, *aHi, *aLo;
    cudaGetSymbolAddress((void**)&cnt, g_cnt);
    cudaGetSymbolAddress((void**)&xh, g_xh);
    cudaGetSymbolAddress((void**)&wHi, g_w_hi);
    cudaGetSymbolAddress((void**)&wLo, g_w_lo);
    cudaGetSymbolAddress((void**)&aHi, g_a_hi);
    cudaGetSymbolAddress((void**)&aLo, g_a_lo);

    // --- prep + CSR build ---
    cudaMemsetAsync(cnt, 0, NN * sizeof(int));
    int nbX = (NN * D / 4 + 255) / 256;
    int nbE = (nE + 255) / 256;
    int nbW = 48;
    prep_hist_kernel<<<nbX + nbE + nbW, 256>>>((const float4*)x, xh, ei, nE,
                                               W1, W2, W3, nbX, nbE);
    int nb = (NN + 1023) / 1024;
    scan1_kernel<<<nb, 1024>>>();
    scan3_kernel<<<(NN + 255) / 256, 256>>>();
    fill_kernel<<<nbE, 256>>>(ei, nE);

    // --- gather -> bf16 hi/lo tile images ---
    gather_kernel<<<(NN + 7) / 8, 256>>>(x);

    // --- fused 3-layer MLP ---
    cudaFuncSetAttribute(mlp3_kernel,
                         cudaFuncAttributeMaxDynamicSharedMemorySize, M3_SM);
    mlp3_kernel<<<NT, 256, M3_SM>>>(aHi, aLo,
                                    wHi,               wLo,
                                    wHi + TILE_U4,     wLo + TILE_U4,
                                    wHi + 2 * TILE_U4, wLo + 2 * TILE_U4,
                                    b1, b2, b3, out);
}

// round 14
// speedup vs baseline: 1.0303x; 1.0303x over previous
#include <cuda_runtime.h>
#include <cuda_bf16.h>
#include <cuda_fp16.h>
#include <cstdint>

#define NN   100000
#define D    128
#define MAXE 3400000
#define NT   ((NN + 127) / 128)
#define TILE_U4 2048   // uint4 per 32KB bf16 128x128 image

// ---------------------------------------------------------------------------
// Allocation-free scratch
// ---------------------------------------------------------------------------
__device__ float  g_h0[(size_t)NN * D];
__device__ __half g_xh[(size_t)NN * D];   // fp16 copy of x (gather operand)
__device__ int    g_cnt[NN];
__device__ int    g_inc[NN];
__device__ int    g_rs[NN];
__device__ int    g_rank[MAXE];           // per-edge rank within its dst list
__device__ int    g_srcs[MAXE];
__device__ int    g_bsums[128];
__device__ uint4  g_w_hi[3 * TILE_U4];
__device__ uint4  g_w_lo[3 * TILE_U4];

static __device__ __forceinline__ uint32_t s2u(const void* p) {
    uint32_t a;
    asm("{ .reg .u64 t; cvta.to.shared.u64 t, %1; cvt.u32.u64 %0, t; }"
        : "=r"(a) : "l"(p));
    return a;
}

static __device__ __forceinline__ uint32_t pack_bf2(float a, float b) {
    __nv_bfloat162 t = __floats2bfloat162_rn(a, b);
    return *(uint32_t*)&t;
}

static __device__ __forceinline__ void mma16816(float* c, const uint32_t* a,
                                                uint32_t b0, uint32_t b1) {
    asm volatile(
        "mma.sync.aligned.m16n8k16.row.col.f32.bf16.bf16.f32 "
        "{%0,%1,%2,%3}, {%4,%5,%6,%7}, {%8,%9}, {%0,%1,%2,%3};"
        : "+f"(c[0]), "+f"(c[1]), "+f"(c[2]), "+f"(c[3])
        : "r"(a[0]), "r"(a[1]), "r"(a[2]), "r"(a[3]), "r"(b0), "r"(b1));
}

static __device__ __forceinline__ void ldsm_x4(uint32_t* r, uint32_t addr) {
    asm volatile("ldmatrix.sync.aligned.m8n8.x4.shared.b16 {%0,%1,%2,%3}, [%4];"
                 : "=r"(r[0]), "=r"(r[1]), "=r"(r[2]), "=r"(r[3]) : "r"(addr));
}
static __device__ __forceinline__ void ldsm_x4t(uint32_t* r, uint32_t addr) {
    asm volatile("ldmatrix.sync.aligned.m8n8.x4.trans.shared.b16 {%0,%1,%2,%3}, [%4];"
                 : "=r"(r[0]), "=r"(r[1]), "=r"(r[2]), "=r"(r[3]) : "r"(addr));
}

static __device__ __forceinline__ void cpa16(uint32_t dst, const void* src) {
    asm volatile("cp.async.cg.shared.global [%0], [%1], 16;"
                 :: "r"(dst), "l"(src) : "memory");
}

// tile byte offset: row-major 128x128 bf16, 256B/row, XOR-swizzled 16B groups
static __device__ __forceinline__ uint32_t toff(int row, int g) {
    return (uint32_t)row * 256u + (uint32_t)((g ^ (row & 7)) << 4);
}

// ---------------------------------------------------------------------------
// x -> fp16 copy
// ---------------------------------------------------------------------------
__global__ void prep_x_kernel(const float4* __restrict__ x4, uint2* __restrict__ xh) {
    int i = blockIdx.x * blockDim.x + threadIdx.x;
    if (i < NN * D / 4) {
        float4 v = x4[i];
        __half2 h0 = __floats2half2_rn(v.x, v.y);
        __half2 h1 = __floats2half2_rn(v.z, v.w);
        xh[i] = make_uint2(*(uint32_t*)&h0, *(uint32_t*)&h1);
    }
}

// ---------------------------------------------------------------------------
// CSR build. hist also records each edge's rank within its destination list
// (the atomicAdd return value), so fill needs no atomics at all.
// ---------------------------------------------------------------------------
__global__ void hist_kernel(const int* __restrict__ ei, int nE) {
    int e = blockIdx.x * blockDim.x + threadIdx.x;
    if (e < nE) g_rank[e] = atomicAdd(&g_cnt[ei[nE + e]], 1);
}

__global__ void scan1_kernel() {
    __shared__ int sm[1024];
    int t = threadIdx.x, b = blockIdx.x;
    int i = b * 1024 + t;
    sm[t] = (i < NN) ? g_cnt[i] : 0;
    __syncthreads();
    #pragma unroll
    for (int off = 1; off < 1024; off <<= 1) {
        int add = (t >= off) ? sm[t - off] : 0;
        __syncthreads();
        sm[t] += add;
        __syncthreads();
    }
    if (i < NN) g_inc[i] = sm[t];
    if (t == 1023) g_bsums[b] = sm[t];
}

// merged scan2+scan3: each block computes its own bsum prefix inline
__global__ void scan3_kernel() {
    __shared__ int base_sh;
    int t = threadIdx.x;
    int chunk = (int)(blockIdx.x >> 2);   // 256-thr blocks, 1024-elem chunks
    if (t < 32) {
        int s = 0;
        for (int j = t; j < chunk; j += 32) s += g_bsums[j];
        #pragma unroll
        for (int o = 16; o; o >>= 1) s += __shfl_down_sync(0xFFFFFFFFu, s, o);
        if (t == 0) base_sh = s;
    }
    __syncthreads();
    int i = blockIdx.x * blockDim.x + t;
    if (i < NN) g_rs[i] = g_inc[i] - g_cnt[i] + base_sh;
}

__global__ void fill_kernel(const int* __restrict__ ei, int nE) {
    int e = blockIdx.x * blockDim.x + threadIdx.x;
    if (e < nE) {
        int s = ei[e], d = ei[nE + e];
        g_srcs[g_rs[d] + g_rank[e]] = s;   // atomic-free scatter
    }
}

// ---------------------------------------------------------------------------
// Prep W: fp32 [k][n] -> bf16 hi/lo swizzled images. grid=3.
// ---------------------------------------------------------------------------
__global__ void prep_w_kernel(const float* __restrict__ W1,
                              const float* __restrict__ W2,
                              const float* __restrict__ W3) {
    const float* W = (blockIdx.x == 0) ? W1 : (blockIdx.x == 1) ? W2 : W3;
    char* hi = (char*)g_w_hi + (size_t)blockIdx.x * 32768;
    char* lo = (char*)g_w_lo + (size_t)blockIdx.x * 32768;
    for (int i = threadIdx.x; i < D * D / 4; i += blockDim.x) {
        int k = i >> 5, c4 = i & 31;
        float4 v = ((const float4*)W)[i];
        float hx = __bfloat162float(__float2bfloat16(v.x));
        float hy = __bfloat162float(__float2bfloat16(v.y));
        float hz = __bfloat162float(__float2bfloat16(v.z));
        float hw = __bfloat162float(__float2bfloat16(v.w));
        uint2 hv = make_uint2(pack_bf2(v.x, v.y), pack_bf2(v.z, v.w));
        uint2 lv = make_uint2(pack_bf2(v.x - hx, v.y - hy), pack_bf2(v.z - hz, v.w - hw));
        uint32_t off = toff(k, c4 >> 1) + (c4 & 1) * 8;
        *(uint2*)(hi + off) = hv;
        *(uint2*)(lo + off) = lv;
    }
}

// ---------------------------------------------------------------------------
// Gather: warp per node. Neighbors from fp16 copy, self fp32; fp32 h0 out.
// ---------------------------------------------------------------------------
static __device__ __forceinline__ void acc_half4(float4& a, uint2 raw) {
    float2 f0 = __half22float2(*(__half2*)&raw.x);
    float2 f1 = __half22float2(*(__half2*)&raw.y);
    a.x += f0.x; a.y += f0.y; a.z += f1.x; a.w += f1.y;
}

__global__ __launch_bounds__(256)
void gather_kernel(const float* __restrict__ x, float* __restrict__ h) {
    int n = blockIdx.x * 8 + (threadIdx.x >> 5);
    if (n >= NN) return;
    int lane = threadIdx.x & 31;
    const uint2* xh = (const uint2*)g_xh;

    float4 a0 = ((const float4*)x)[(size_t)n * 32 + lane];   // self, fp32
    float4 a1 = make_float4(0.f, 0.f, 0.f, 0.f);
    float4 a2 = a1, a3 = a1;

    int start = g_rs[n], c = g_cnt[n];
    const int* sp = g_srcs + start;
    int j = 0;
    for (; j + 4 <= c; j += 4) {
        int s0 = sp[j], s1 = sp[j + 1], s2 = sp[j + 2], s3 = sp[j + 3];
        uint2 v0 = xh[(size_t)s0 * 32 + lane];
        uint2 v1 = xh[(size_t)s1 * 32 + lane];
        uint2 v2 = xh[(size_t)s2 * 32 + lane];
        uint2 v3 = xh[(size_t)s3 * 32 + lane];
        acc_half4(a0, v0); acc_half4(a1, v1);
        acc_half4(a2, v2); acc_half4(a3, v3);
    }
    for (; j < c; j++)
        acc_half4(a0, xh[(size_t)sp[j] * 32 + lane]);

    float4 s;
    s.x = (a0.x + a1.x) + (a2.x + a3.x);
    s.y = (a0.y + a1.y) + (a2.y + a3.y);
    s.z = (a0.z + a1.z) + (a2.z + a3.z);
    s.w = (a0.w + a1.w) + (a2.w + a3.w);
    ((float4*)h)[(size_t)n * 32 + lane] = s;
}

// ---------------------------------------------------------------------------
// GEMM building blocks (split-bf16 HMMA, 128x128 tile, K=128), R9 shapes.
// lo image always at +32768 within its region.
// ---------------------------------------------------------------------------
static __device__ __forceinline__ void mma_mainloop(
    uint32_t sb, uint32_t w_off, uint32_t a_off, int wid, int lane,
    float acc[16][4]) {
    #pragma unroll
    for (int i = 0; i < 16; i++)
        #pragma unroll
        for (int j = 0; j < 4; j++) acc[i][j] = 0.f;

    int mrow = wid * 16;
    int arow = mrow + (lane & 15);
    int asel = lane >> 4;
    int axor = arow & 7;
    uint32_t a_base = sb + a_off + (uint32_t)arow * 256u;
    int brow = lane & 15;
    int bsel = lane >> 4;

    #pragma unroll
    for (int ks = 0; ks < 8; ks++) {
        uint32_t ag = (uint32_t)(((ks * 2 + asel) ^ axor) << 4);
        uint32_t ahi[4], alo[4];
        ldsm_x4(ahi, a_base + ag);
        ldsm_x4(alo, a_base + 32768u + ag);

        int brr = ks * 16 + brow;
        uint32_t b_base = sb + w_off + (uint32_t)brr * 256u;
        int bxor = brr & 7;

        #pragma unroll
        for (int p = 0; p < 8; p++) {
            uint32_t bg = (uint32_t)(((p * 2 + bsel) ^ bxor) << 4);
            uint32_t bh[4], bl[4];
            ldsm_x4t(bh, b_base + bg);
            ldsm_x4t(bl, b_base + 32768u + bg);
            mma16816(acc[2 * p],     ahi, bh[0], bh[1]);
            mma16816(acc[2 * p + 1], ahi, bh[2], bh[3]);
            mma16816(acc[2 * p],     ahi, bl[0], bl[1]);
            mma16816(acc[2 * p + 1], ahi, bl[2], bl[3]);
            mma16816(acc[2 * p],     alo, bh[0], bh[1]);
            mma16816(acc[2 * p + 1], alo, bh[2], bh[3]);
        }
    }
}

// bias + relu -> fp32 gmem rows
static __device__ __forceinline__ void epilogue_gmem(
    float acc[16][4], const float* bs, int wid, int lane, int row0,
    float* __restrict__ hout) {
    int rbase = wid * 16 + (lane >> 2);
    int col0 = (lane & 3) * 2;
    #pragma unroll
    for (int half = 0; half < 2; half++) {
        int grow = row0 + rbase + half * 8;
        if (grow < NN) {
            float* op = hout + (size_t)grow * D;
            #pragma unroll
            for (int nt = 0; nt < 16; nt++) {
                int c = nt * 8 + col0;
                float2 o;
                o.x = fmaxf(acc[nt][half * 2 + 0] + bs[c], 0.f);
                o.y = fmaxf(acc[nt][half * 2 + 1] + bs[c + 1], 0.f);
                *(float2*)(op + c) = o;
            }
        }
    }
}

// bias + relu -> bf16 hi/lo smem tile images (next GEMM's A operand)
static __device__ __forceinline__ void epilogue_smem(
    float acc[16][4], const float* bs, int wid, int lane,
    char* smem, uint32_t a_off) {
    int rbase = wid * 16 + (lane >> 2);
    int col0 = (lane & 3) * 2;
    #pragma unroll
    for (int half = 0; half < 2; half++) {
        int row = rbase + half * 8;
        #pragma unroll
        for (int nt = 0; nt < 16; nt++) {
            int c = nt * 8 + col0;
            float v0 = fmaxf(acc[nt][half * 2 + 0] + bs[c], 0.f);
            float v1 = fmaxf(acc[nt][half * 2 + 1] + bs[c + 1], 0.f);
            float h0 = __bfloat162float(__float2bfloat16(v0));
            float h1 = __bfloat162float(__float2bfloat16(v1));
            uint32_t off = toff(row, nt) + (uint32_t)col0 * 2u;
            *(uint32_t*)(smem + a_off + off) = pack_bf2(v0, v1);
            *(uint32_t*)(smem + a_off + 32768u + off) = pack_bf2(v0 - h0, v1 - h1);
        }
    }
}

// stage fp32 rows -> bf16 hi/lo swizzled A images in smem
static __device__ __forceinline__ void stage_a(
    char* smem, uint32_t a_off, const float* __restrict__ hin,
    int row0, int tid) {
    #pragma unroll
    for (int t = 0; t < 16; t++) {
        int i = tid + t * 256;
        int row = i >> 5, c4 = i & 31;
        int grow = row0 + row;
        float4 v = make_float4(0.f, 0.f, 0.f, 0.f);
        if (grow < NN) v = ((const float4*)(hin + (size_t)grow * D))[c4];
        float hx = __bfloat162float(__float2bfloat16(v.x));
        float hy = __bfloat162float(__float2bfloat16(v.y));
        float hz = __bfloat162float(__float2bfloat16(v.z));
        float hw = __bfloat162float(__float2bfloat16(v.w));
        uint2 hv = make_uint2(pack_bf2(v.x, v.y), pack_bf2(v.z, v.w));
        uint2 lv = make_uint2(pack_bf2(v.x - hx, v.y - hy), pack_bf2(v.z - hz, v.w - hw));
        uint32_t off = toff(row, c4 >> 1) + (c4 & 1) * 8;
        *(uint2*)(smem + a_off + off) = hv;
        *(uint2*)(smem + a_off + 32768u + off) = lv;
    }
}

// ---------------------------------------------------------------------------
// All 3 layers in one kernel, one CTA per 128-row tile (R12 structure).
// ---------------------------------------------------------------------------
#define R1_OFF 0u
#define R2_OFF 65536u
#define R3_OFF 131072u
#define B1_OFF 196608u
#define B2_OFF 197120u
#define B3_OFF 197632u
#define M3_SM  (196608 + 1536)

__global__ __launch_bounds__(256, 1)
void mlp3_kernel(const float* __restrict__ hin,
                 const uint4* __restrict__ W1hi, const uint4* __restrict__ W1lo,
                 const uint4* __restrict__ W2hi, const uint4* __restrict__ W2lo,
                 const uint4* __restrict__ W3hi, const uint4* __restrict__ W3lo,
                 const float* __restrict__ b1, const float* __restrict__ b2,
                 const float* __restrict__ b3,
                 float* __restrict__ out) {
    extern __shared__ char smem[];
    uint32_t sb = s2u(smem);
    int tid = threadIdx.x, wid = tid >> 5, lane = tid & 31;
    int row0 = blockIdx.x * 128;

    // W1/W2 via cp.async — flows while stage_a's fp32 loads + converts run
    #pragma unroll
    for (int t = 0; t < 8; t++) {
        int i = tid + t * 256;
        cpa16(sb + R1_OFF + (uint32_t)i * 16u,          W1hi + i);
        cpa16(sb + R1_OFF + 32768u + (uint32_t)i * 16u, W1lo + i);
        cpa16(sb + R2_OFF + (uint32_t)i * 16u,          W2hi + i);
        cpa16(sb + R2_OFF + 32768u + (uint32_t)i * 16u, W2lo + i);
    }
    asm volatile("cp.async.commit_group;" ::: "memory");

    stage_a(smem, R3_OFF, hin, row0, tid);
    if (tid < 32)       ((float4*)(smem + B1_OFF))[tid]      = ((const float4*)b1)[tid];
    else if (tid < 64)  ((float4*)(smem + B2_OFF))[tid - 32] = ((const float4*)b2)[tid - 32];
    else if (tid < 96)  ((float4*)(smem + B3_OFF))[tid - 64] = ((const float4*)b3)[tid - 64];

    asm volatile("cp.async.wait_group 0;" ::: "memory");
    __syncthreads();

    float acc[16][4];
    // GEMM1
    mma_mainloop(sb, R1_OFF, R3_OFF, wid, lane, acc);
    __syncthreads();   // done reading R1(W1), R3(A)

    // W3 -> R3, hidden under GEMM2
    #pragma unroll
    for (int t = 0; t < 8; t++) {
        int i = tid + t * 256;
        cpa16(sb + R3_OFF + (uint32_t)i * 16u,          W3hi + i);
        cpa16(sb + R3_OFF + 32768u + (uint32_t)i * 16u, W3lo + i);
    }
    asm volatile("cp.async.commit_group;" ::: "memory");

    epilogue_smem(acc, (const float*)(smem + B1_OFF), wid, lane, smem, R1_OFF);
    __syncthreads();   // A' visible

    // GEMM2
    mma_mainloop(sb, R2_OFF, R1_OFF, wid, lane, acc);
    asm volatile("cp.async.wait_group 0;" ::: "memory");
    __syncthreads();   // done reading R1(A'); W3 landed

    epilogue_smem(acc, (const float*)(smem + B2_OFF), wid, lane, smem, R1_OFF);
    __syncthreads();   // A'' visible

    // GEMM3
    mma_mainloop(sb, R3_OFF, R1_OFF, wid, lane, acc);
    epilogue_gmem(acc, (const float*)(smem + B3_OFF), wid, lane, row0, out);
}

// ---------------------------------------------------------------------------
extern "C" void kernel_launch(void* const* d_in, const int* in_sizes, int n_in,
                              void* d_out, int out_size) {
    const float* x  = (const float*)d_in[0];
    const float* W1 = (const float*)d_in[1];
    const float* b1 = (const float*)d_in[2];
    const float* W2 = (const float*)d_in[3];
    const float* b2 = (const float*)d_in[4];
    const float* W3 = (const float*)d_in[5];
    const float* b3 = (const float*)d_in[6];
    const int*   ei = (const int*)d_in[7];   // int32 (JAX x64 disabled)
    float* out = (float*)d_out;

    int nE = in_sizes[7] / 2;
    if (nE > MAXE) nE = MAXE;

    float* h0;
    int* cnt;
    uint2* xh;
    uint4 *wHi, *wLo;
    cudaGetSymbolAddress((void**)&h0, g_h0);
    cudaGetSymbolAddress((void**)&cnt, g_cnt);
    cudaGetSymbolAddress((void**)&xh, g_xh);
    cudaGetSymbolAddress((void**)&wHi, g_w_hi);
    cudaGetSymbolAddress((void**)&wLo, g_w_lo);

    // --- prep + CSR build ---
    cudaMemsetAsync(cnt, 0, NN * sizeof(int));
    prep_x_kernel<<<(NN * D / 4 + 255) / 256, 256>>>((const float4*)x, xh);
    prep_w_kernel<<<3, 256>>>(W1, W2, W3);
    hist_kernel<<<(nE + 255) / 256, 256>>>(ei, nE);
    int nb = (NN + 1023) / 1024;
    scan1_kernel<<<nb, 1024>>>();
    scan3_kernel<<<(NN + 255) / 256, 256>>>();
    fill_kernel<<<(nE + 255) / 256, 256>>>(ei, nE);

    // --- gather: h0 = x + segment_sum(x[src] -> dst), fp16 neighbor reads ---
    gather_kernel<<<(NN + 7) / 8, 256>>>(x, h0);

    // --- fused 3-layer MLP ---
    cudaFuncSetAttribute(mlp3_kernel,
                         cudaFuncAttributeMaxDynamicSharedMemorySize, M3_SM);
    mlp3_kernel<<<NT, 256, M3_SM>>>(h0,
                                    wHi,               wLo,
                                    wHi + TILE_U4,     wLo + TILE_U4,
                                    wHi + 2 * TILE_U4, wLo + 2 * TILE_U4,
                                    b1, b2, b3, out);
}

// round 16
// speedup vs baseline: 1.0653x; 1.0339x over previous
#include <cuda_runtime.h>
#include <cuda_bf16.h>
#include <cuda_fp16.h>
#include <cstdint>

#define NN   100000
#define D    128
#define MAXE 3400000
#define NT   ((NN + 127) / 128)
#define TILE_U4 2048   // uint4 per 32KB bf16 128x128 image

// ---------------------------------------------------------------------------
// Allocation-free scratch
// ---------------------------------------------------------------------------
__device__ float  g_h0[(size_t)NN * D];
__device__ __half g_xh[(size_t)NN * D];   // fp16 copy of x (gather operand)
__device__ int    g_cnt[NN];
__device__ int    g_inc[NN];
__device__ int    g_rs[NN];
__device__ int    g_rank[MAXE];           // per-edge rank within its dst list
__device__ int    g_srcs[MAXE];
__device__ int    g_bsums[128];
__device__ uint4  g_w_hi[3 * TILE_U4];
__device__ uint4  g_w_lo[3 * TILE_U4];

static __device__ __forceinline__ uint32_t s2u(const void* p) {
    uint32_t a;
    asm("{ .reg .u64 t; cvta.to.shared.u64 t, %1; cvt.u32.u64 %0, t; }"
        : "=r"(a) : "l"(p));
    return a;
}

static __device__ __forceinline__ uint32_t pack_bf2(float a, float b) {
    __nv_bfloat162 t = __floats2bfloat162_rn(a, b);
    return *(uint32_t*)&t;
}

static __device__ __forceinline__ void mma16816(float* c, const uint32_t* a,
                                                uint32_t b0, uint32_t b1) {
    asm volatile(
        "mma.sync.aligned.m16n8k16.row.col.f32.bf16.bf16.f32 "
        "{%0,%1,%2,%3}, {%4,%5,%6,%7}, {%8,%9}, {%0,%1,%2,%3};"
        : "+f"(c[0]), "+f"(c[1]), "+f"(c[2]), "+f"(c[3])
        : "r"(a[0]), "r"(a[1]), "r"(a[2]), "r"(a[3]), "r"(b0), "r"(b1));
}

static __device__ __forceinline__ void ldsm_x4(uint32_t* r, uint32_t addr) {
    asm volatile("ldmatrix.sync.aligned.m8n8.x4.shared.b16 {%0,%1,%2,%3}, [%4];"
                 : "=r"(r[0]), "=r"(r[1]), "=r"(r[2]), "=r"(r[3]) : "r"(addr));
}
static __device__ __forceinline__ void ldsm_x4t(uint32_t* r, uint32_t addr) {
    asm volatile("ldmatrix.sync.aligned.m8n8.x4.trans.shared.b16 {%0,%1,%2,%3}, [%4];"
                 : "=r"(r[0]), "=r"(r[1]), "=r"(r[2]), "=r"(r[3]) : "r"(addr));
}

static __device__ __forceinline__ void cpa16(uint32_t dst, const void* src) {
    asm volatile("cp.async.cg.shared.global [%0], [%1], 16;"
                 :: "r"(dst), "l"(src) : "memory");
}

// tile byte offset: row-major 128x128 bf16, 256B/row, XOR-swizzled 16B groups
static __device__ __forceinline__ uint32_t toff(int row, int g) {
    return (uint32_t)row * 256u + (uint32_t)((g ^ (row & 7)) << 4);
}

// ---------------------------------------------------------------------------
// Merged prep: [0,nbX) x->fp16 copy; [nbX,nbX+nbE) hist(+rank); rest W images.
// ---------------------------------------------------------------------------
__global__ void prep_hist_kernel(const float4* __restrict__ x4,
                                 uint2* __restrict__ xh,
                                 const int* __restrict__ ei, int nE,
                                 const float* __restrict__ W1,
                                 const float* __restrict__ W2,
                                 const float* __restrict__ W3,
                                 int nbX, int nbE) {
    int b = blockIdx.x;
    if (b < nbX) {
        int i = b * 256 + threadIdx.x;
        if (i < NN * D / 4) {
            float4 v = x4[i];
            __half2 h0 = __floats2half2_rn(v.x, v.y);
            __half2 h1 = __floats2half2_rn(v.z, v.w);
            xh[i] = make_uint2(*(uint32_t*)&h0, *(uint32_t*)&h1);
        }
    } else if (b < nbX + nbE) {
        int e = (b - nbX) * 256 + threadIdx.x;
        if (e < nE) g_rank[e] = atomicAdd(&g_cnt[ei[nE + e]], 1);
    } else {
        int idx = (b - nbX - nbE) * 256 + threadIdx.x;   // 48 blocks: 3*4096
        if (idx < 3 * 4096) {
            int w = idx >> 12, i = idx & 4095;
            const float* W = (w == 0) ? W1 : (w == 1) ? W2 : W3;
            char* hi = (char*)g_w_hi + (size_t)w * 32768;
            char* lo = (char*)g_w_lo + (size_t)w * 32768;
            int k = i >> 5, c4 = i & 31;
            float4 v = ((const float4*)W)[i];
            float hx = __bfloat162float(__float2bfloat16(v.x));
            float hy = __bfloat162float(__float2bfloat16(v.y));
            float hz = __bfloat162float(__float2bfloat16(v.z));
            float hw = __bfloat162float(__float2bfloat16(v.w));
            uint2 hv = make_uint2(pack_bf2(v.x, v.y), pack_bf2(v.z, v.w));
            uint2 lv = make_uint2(pack_bf2(v.x - hx, v.y - hy),
                                  pack_bf2(v.z - hz, v.w - hw));
            uint32_t off = toff(k, c4 >> 1) + (c4 & 1) * 8;
            *(uint2*)(hi + off) = hv;
            *(uint2*)(lo + off) = lv;
        }
    }
}

// ---------------------------------------------------------------------------
// scan1: two-level warp-shuffle inclusive scan over 1024-element chunks.
// ---------------------------------------------------------------------------
__global__ void scan1_kernel() {
    __shared__ int warp_sums[32];
    int t = threadIdx.x, b = blockIdx.x;
    int i = b * 1024 + t;
    int lane = t & 31, w = t >> 5;
    int s = (i < NN) ? g_cnt[i] : 0;
    #pragma unroll
    for (int o = 1; o < 32; o <<= 1) {
        int n = __shfl_up_sync(0xFFFFFFFFu, s, o);
        if (lane >= o) s += n;
    }
    if (lane == 31) warp_sums[w] = s;
    __syncthreads();
    if (w == 0) {
        int ws = warp_sums[lane];
        #pragma unroll
        for (int o = 1; o < 32; o <<= 1) {
            int n = __shfl_up_sync(0xFFFFFFFFu, ws, o);
            if (lane >= o) ws += n;
        }
        warp_sums[lane] = ws;
    }
    __syncthreads();
    if (w > 0) s += warp_sums[w - 1];
    if (i < NN) g_inc[i] = s;
    if (t == 1023) g_bsums[b] = s;
}

// merged scan2+scan3: each block computes its own bsum prefix inline
__global__ void scan3_kernel() {
    __shared__ int base_sh;
    int t = threadIdx.x;
    int chunk = (int)(blockIdx.x >> 2);   // 256-thr blocks, 1024-elem chunks
    if (t < 32) {
        int s = 0;
        for (int j = t; j < chunk; j += 32) s += g_bsums[j];
        #pragma unroll
        for (int o = 16; o; o >>= 1) s += __shfl_down_sync(0xFFFFFFFFu, s, o);
        if (t == 0) base_sh = s;
    }
    __syncthreads();
    int i = blockIdx.x * blockDim.x + t;
    if (i < NN) g_rs[i] = g_inc[i] - g_cnt[i] + base_sh;
}

__global__ void fill_kernel(const int* __restrict__ ei, int nE) {
    int e = blockIdx.x * blockDim.x + threadIdx.x;
    if (e < nE) {
        int s = ei[e], d = ei[nE + e];
        g_srcs[g_rs[d] + g_rank[e]] = s;   // atomic-free scatter
    }
}

// ---------------------------------------------------------------------------
// Gather: warp per node. Neighbors from fp16 copy, self fp32; fp32 h0 out.
// ---------------------------------------------------------------------------
static __device__ __forceinline__ void acc_half4(float4& a, uint2 raw) {
    float2 f0 = __half22float2(*(__half2*)&raw.x);
    float2 f1 = __half22float2(*(__half2*)&raw.y);
    a.x += f0.x; a.y += f0.y; a.z += f1.x; a.w += f1.y;
}

__global__ __launch_bounds__(256)
void gather_kernel(const float* __restrict__ x, float* __restrict__ h) {
    int n = blockIdx.x * 8 + (threadIdx.x >> 5);
    if (n >= NN) return;
    int lane = threadIdx.x & 31;
    const uint2* xh = (const uint2*)g_xh;

    float4 a0 = ((const float4*)x)[(size_t)n * 32 + lane];   // self, fp32
    float4 a1 = make_float4(0.f, 0.f, 0.f, 0.f);
    float4 a2 = a1, a3 = a1;

    int start = g_rs[n], c = g_cnt[n];
    const int* sp = g_srcs + start;
    int j = 0;
    for (; j + 4 <= c; j += 4) {
        int s0 = sp[j], s1 = sp[j + 1], s2 = sp[j + 2], s3 = sp[j + 3];
        uint2 v0 = xh[(size_t)s0 * 32 + lane];
        uint2 v1 = xh[(size_t)s1 * 32 + lane];
        uint2 v2 = xh[(size_t)s2 * 32 + lane];
        uint2 v3 = xh[(size_t)s3 * 32 + lane];
        acc_half4(a0, v0); acc_half4(a1, v1);
        acc_half4(a2, v2); acc_half4(a3, v3);
    }
    for (; j < c; j++)
        acc_half4(a0, xh[(size_t)sp[j] * 32 + lane]);

    float4 s;
    s.x = (a0.x + a1.x) + (a2.x + a3.x);
    s.y = (a0.y + a1.y) + (a2.y + a3.y);
    s.z = (a0.z + a1.z) + (a2.z + a3.z);
    s.w = (a0.w + a1.w) + (a2.w + a3.w);
    ((float4*)h)[(size_t)n * 32 + lane] = s;
}

// ---------------------------------------------------------------------------
// GEMM building blocks (split-bf16 HMMA, 128x128 tile, K=128), R9 shapes.
// lo image always at +32768 within its region.
// ---------------------------------------------------------------------------
static __device__ __forceinline__ void mma_mainloop(
    uint32_t sb, uint32_t w_off, uint32_t a_off, int wid, int lane,
    float acc[16][4]) {
    #pragma unroll
    for (int i = 0; i < 16; i++)
        #pragma unroll
        for (int j = 0; j < 4; j++) acc[i][j] = 0.f;

    int mrow = wid * 16;
    int arow = mrow + (lane & 15);
    int asel = lane >> 4;
    int axor = arow & 7;
    uint32_t a_base = sb + a_off + (uint32_t)arow * 256u;
    int brow = lane & 15;
    int bsel = lane >> 4;

    #pragma unroll
    for (int ks = 0; ks < 8; ks++) {
        uint32_t ag = (uint32_t)(((ks * 2 + asel) ^ axor) << 4);
        uint32_t ahi[4], alo[4];
        ldsm_x4(ahi, a_base + ag);
        ldsm_x4(alo, a_base + 32768u + ag);

        int brr = ks * 16 + brow;
        uint32_t b_base = sb + w_off + (uint32_t)brr * 256u;
        int bxor = brr & 7;

        #pragma unroll
        for (int p = 0; p < 8; p++) {
            uint32_t bg = (uint32_t)(((p * 2 + bsel) ^ bxor) << 4);
            uint32_t bh[4], bl[4];
            ldsm_x4t(bh, b_base + bg);
            ldsm_x4t(bl, b_base + 32768u + bg);
            mma16816(acc[2 * p],     ahi, bh[0], bh[1]);
            mma16816(acc[2 * p + 1], ahi, bh[2], bh[3]);
            mma16816(acc[2 * p],     ahi, bl[0], bl[1]);
            mma16816(acc[2 * p + 1], ahi, bl[2], bl[3]);
            mma16816(acc[2 * p],     alo, bh[0], bh[1]);
            mma16816(acc[2 * p + 1], alo, bh[2], bh[3]);
        }
    }
}

// bias + relu -> fp32 gmem rows
static __device__ __forceinline__ void epilogue_gmem(
    float acc[16][4], const float* bs, int wid, int lane, int row0,
    float* __restrict__ hout) {
    int rbase = wid * 16 + (lane >> 2);
    int col0 = (lane & 3) * 2;
    #pragma unroll
    for (int half = 0; half < 2; half++) {
        int grow = row0 + rbase + half * 8;
        if (grow < NN) {
            float* op = hout + (size_t)grow * D;
            #pragma unroll
            for (int nt = 0; nt < 16; nt++) {
                int c = nt * 8 + col0;
                float2 o;
                o.x = fmaxf(acc[nt][half * 2 + 0] + bs[c], 0.f);
                o.y = fmaxf(acc[nt][half * 2 + 1] + bs[c + 1], 0.f);
                *(float2*)(op + c) = o;
            }
        }
    }
}

// bias + relu -> bf16 hi/lo smem tile images (next GEMM's A operand)
static __device__ __forceinline__ void epilogue_smem(
    float acc[16][4], const float* bs, int wid, int lane,
    char* smem, uint32_t a_off) {
    int rbase = wid * 16 + (lane >> 2);
    int col0 = (lane & 3) * 2;
    #pragma unroll
    for (int half = 0; half < 2; half++) {
        int row = rbase + half * 8;
        #pragma unroll
        for (int nt = 0; nt < 16; nt++) {
            int c = nt * 8 + col0;
            float v0 = fmaxf(acc[nt][half * 2 + 0] + bs[c], 0.f);
            float v1 = fmaxf(acc[nt][half * 2 + 1] + bs[c + 1], 0.f);
            float h0 = __bfloat162float(__float2bfloat16(v0));
            float h1 = __bfloat162float(__float2bfloat16(v1));
            uint32_t off = toff(row, nt) + (uint32_t)col0 * 2u;
            *(uint32_t*)(smem + a_off + off) = pack_bf2(v0, v1);
            *(uint32_t*)(smem + a_off + 32768u + off) = pack_bf2(v0 - h0, v1 - h1);
        }
    }
}

// stage fp32 rows -> bf16 hi/lo swizzled A images in smem
static __device__ __forceinline__ void stage_a(
    char* smem, uint32_t a_off, const float* __restrict__ hin,
    int row0, int tid) {
    #pragma unroll
    for (int t = 0; t < 16; t++) {
        int i = tid + t * 256;
        int row = i >> 5, c4 = i & 31;
        int grow = row0 + row;
        float4 v = make_float4(0.f, 0.f, 0.f, 0.f);
        if (grow < NN) v = ((const float4*)(hin + (size_t)grow * D))[c4];
        float hx = __bfloat162float(__float2bfloat16(v.x));
        float hy = __bfloat162float(__float2bfloat16(v.y));
        float hz = __bfloat162float(__float2bfloat16(v.z));
        float hw = __bfloat162float(__float2bfloat16(v.w));
        uint2 hv = make_uint2(pack_bf2(v.x, v.y), pack_bf2(v.z, v.w));
        uint2 lv = make_uint2(pack_bf2(v.x - hx, v.y - hy), pack_bf2(v.z - hz, v.w - hw));
        uint32_t off = toff(row, c4 >> 1) + (c4 & 1) * 8;
        *(uint2*)(smem + a_off + off) = hv;
        *(uint2*)(smem + a_off + 32768u + off) = lv;
    }
}

// ---------------------------------------------------------------------------
// All 3 layers in one kernel, one CTA per 128-row tile (R12/R14 structure).
// ---------------------------------------------------------------------------
#define R1_OFF 0u
#define R2_OFF 65536u
#define R3_OFF 131072u
#define B1_OFF 196608u
#define B2_OFF 197120u
#define B3_OFF 197632u
#define M3_SM  (196608 + 1536)

__global__ __launch_bounds__(256, 1)
void mlp3_kernel(const float* __restrict__ hin,
                 const uint4* __restrict__ W1hi, const uint4* __restrict__ W1lo,
                 const uint4* __restrict__ W2hi, const uint4* __restrict__ W2lo,
                 const uint4* __restrict__ W3hi, const uint4* __restrict__ W3lo,
                 const float* __restrict__ b1, const float* __restrict__ b2,
                 const float* __restrict__ b3,
                 float* __restrict__ out) {
    extern __shared__ char smem[];
    uint32_t sb = s2u(smem);
    int tid = threadIdx.x, wid = tid >> 5, lane = tid & 31;
    int row0 = blockIdx.x * 128;

    // W1/W2 via cp.async — flows while stage_a's fp32 loads + converts run
    #pragma unroll
    for (int t = 0; t < 8; t++) {
        int i = tid + t * 256;
        cpa16(sb + R1_OFF + (uint32_t)i * 16u,          W1hi + i);
        cpa16(sb + R1_OFF + 32768u + (uint32_t)i * 16u, W1lo + i);
        cpa16(sb + R2_OFF + (uint32_t)i * 16u,          W2hi + i);
        cpa16(sb + R2_OFF + 32768u + (uint32_t)i * 16u, W2lo + i);
    }
    asm volatile("cp.async.commit_group;" ::: "memory");

    stage_a(smem, R3_OFF, hin, row0, tid);
    if (tid < 32)       ((float4*)(smem + B1_OFF))[tid]      = ((const float4*)b1)[tid];
    else if (tid < 64)  ((float4*)(smem + B2_OFF))[tid - 32] = ((const float4*)b2)[tid - 32];
    else if (tid < 96)  ((float4*)(smem + B3_OFF))[tid - 64] = ((const float4*)b3)[tid - 64];

    asm volatile("cp.async.wait_group 0;" ::: "memory");
    __syncthreads();

    float acc[16][4];
    // GEMM1
    mma_mainloop(sb, R1_OFF, R3_OFF, wid, lane, acc);
    __syncthreads();   // done reading R1(W1), R3(A)

    // W3 -> R3, hidden under GEMM2
    #pragma unroll
    for (int t = 0; t < 8; t++) {
        int i = tid + t * 256;
        cpa16(sb + R3_OFF + (uint32_t)i * 16u,          W3hi + i);
        cpa16(sb + R3_OFF + 32768u + (uint32_t)i * 16u, W3lo + i);
    }
    asm volatile("cp.async.commit_group;" ::: "memory");

    epilogue_smem(acc, (const float*)(smem + B1_OFF), wid, lane, smem, R1_OFF);
    __syncthreads();   // A' visible

    // GEMM2
    mma_mainloop(sb, R2_OFF, R1_OFF, wid, lane, acc);
    asm volatile("cp.async.wait_group 0;" ::: "memory");
    __syncthreads();   // done reading R1(A'); W3 landed

    epilogue_smem(acc, (const float*)(smem + B2_OFF), wid, lane, smem, R1_OFF);
    __syncthreads();   // A'' visible

    // GEMM3
    mma_mainloop(sb, R3_OFF, R1_OFF, wid, lane, acc);
    epilogue_gmem(acc, (const float*)(smem + B3_OFF), wid, lane, row0, out);
}

// ---------------------------------------------------------------------------
extern "C" void kernel_launch(void* const* d_in, const int* in_sizes, int n_in,
                              void* d_out, int out_size) {
    const float* x  = (const float*)d_in[0];
    const float* W1 = (const float*)d_in[1];
    const float* b1 = (const float*)d_in[2];
    const float* W2 = (const float*)d_in[3];
    const float* b2 = (const float*)d_in[4];
    const float* W3 = (const float*)d_in[5];
    const float* b3 = (const float*)d_in[6];
    const int*   ei = (const int*)d_in[7];   // int32 (JAX x64 disabled)
    float* out = (float*)d_out;

    int nE = in_sizes[7] / 2;
    if (nE > MAXE) nE = MAXE;

    float* h0;
    int* cnt;
    uint2* xh;
    uint4 *wHi, *wLo;
    cudaGetSymbolAddress((void**)&h0, g_h0);
    cudaGetSymbolAddress((void**)&cnt, g_cnt);
    cudaGetSymbolAddress((void**)&xh, g_xh);
    cudaGetSymbolAddress((void**)&wHi, g_w_hi);
    cudaGetSymbolAddress((void**)&wLo, g_w_lo);

    // --- prep + CSR build ---
    cudaMemsetAsync(cnt, 0, NN * sizeof(int));
    int nbX = (NN * D / 4 + 255) / 256;
    int nbE = (nE + 255) / 256;
    prep_hist_kernel<<<nbX + nbE + 48, 256>>>((const float4*)x, xh, ei, nE,
                                              W1, W2, W3, nbX, nbE);
    int nb = (NN + 1023) / 1024;
    scan1_kernel<<<nb, 1024>>>();
    scan3_kernel<<<(NN + 255) / 256, 256>>>();
    fill_kernel<<<nbE, 256>>>(ei, nE);

    // --- gather: h0 = x + segment_sum(x[src] -> dst), fp16 neighbor reads ---
    gather_kernel<<<(NN + 7) / 8, 256>>>(x, h0);

    // --- fused 3-layer MLP ---
    cudaFuncSetAttribute(mlp3_kernel,
                         cudaFuncAttributeMaxDynamicSharedMemorySize, M3_SM);
    mlp3_kernel<<<NT, 256, M3_SM>>>(h0,
                                    wHi,               wLo,
                                    wHi + TILE_U4,     wLo + TILE_U4,
                                    wHi + 2 * TILE_U4, wLo + 2 * TILE_U4,
                                    b1, b2, b3, out);
}